// round 17
// baseline (speedup 1.0000x reference)
#include <cuda_runtime.h>
#include <cuda_bf16.h>
#include <cstdint>
#include <math.h>

#define Bb 128
#define Tt 1024
#define Nn 256
#define Mm 256
#define Gg 768
#define ROWS (Bb*Tt)

// Scratch (allocation-free rule: __device__ globals)
__device__ float g_gx[(size_t)ROWS * Gg];    // input-gate activations
__device__ float g_out0[(size_t)ROWS * Mm];  // layer-0 output

typedef unsigned long long u64t;

// ---------------- packed f32x2 helpers ----------------
__device__ __forceinline__ u64t ffma2(u64t a, u64t b, u64t c) {
    u64t d;
    asm("fma.rn.f32x2 %0, %1, %2, %3;" : "=l"(d) : "l"(a), "l"(b), "l"(c));
    return d;
}
__device__ __forceinline__ float2 unpack2(u64t v) {
    float2 r; asm("mov.b64 {%0, %1}, %2;" : "=f"(r.x), "=f"(r.y) : "l"(v)); return r;
}

// ---------------- cluster / DSMEM helpers ----------------
__device__ __forceinline__ uint32_t smem_u32(const void* p) {
    uint32_t a;
    asm("{ .reg .u64 t; cvta.to.shared.u64 t, %1; cvt.u32.u64 %0, t; }" : "=r"(a) : "l"(p));
    return a;
}
__device__ __forceinline__ uint32_t cl_rank() {
    uint32_t r; asm("mov.u32 %0, %%cluster_ctarank;" : "=r"(r)); return r;
}
__device__ __forceinline__ uint32_t cl_map(uint32_t addr, uint32_t rank) {
    uint32_t r; asm("mapa.shared::cluster.u32 %0, %1, %2;" : "=r"(r) : "r"(addr), "r"(rank)); return r;
}
__device__ __forceinline__ void st_cl_f32(uint32_t addr, float v) {
    asm volatile("st.shared::cluster.f32 [%0], %1;" :: "r"(addr), "f"(v) : "memory");
}
__device__ __forceinline__ void cl_sync() {
    asm volatile("barrier.cluster.arrive.aligned;" ::: "memory");
    asm volatile("barrier.cluster.wait.aligned;" ::: "memory");
}

// ---------------- mbarrier helpers ----------------
__device__ __forceinline__ void mbar_init(uint32_t a, uint32_t cnt) {
    asm volatile("mbarrier.init.shared.b64 [%0], %1;" :: "r"(a), "r"(cnt) : "memory");
}
// release-arrive on a PREMAPPED cluster address
__device__ __forceinline__ void mbar_arrive_rel_pre(uint32_t mapped_addr) {
    asm volatile("mbarrier.arrive.release.cluster.shared::cluster.b64 _, [%0];"
                 :: "r"(mapped_addr) : "memory");
}
__device__ __forceinline__ void mbar_wait_parity_cluster(uint32_t a, uint32_t parity) {
    asm volatile(
        "{\n\t.reg .pred P1;\n\t"
        "WL_%=:\n\t"
        "mbarrier.try_wait.parity.acquire.cluster.shared::cta.b64 P1, [%0], %1, 0x989680;\n\t"
        "@P1 bra.uni WD_%=;\n\t"
        "bra.uni WL_%=;\n\t"
        "WD_%=:\n\t}"
        :: "r"(a), "r"(parity) : "memory");
}

__device__ __forceinline__ float fast_sigmoid(float x) {
    return 1.f / (1.f + __expf(-x));
}
__device__ __forceinline__ float fast_tanh(float x) {
    return 1.f - __fdividef(2.f, 1.f + __expf(2.f * x));
}

// ---------------- warp-MMA helpers (baseline ISA, no tcgen05) ----------------
__device__ __forceinline__ void ldsm4(uint32_t r[4], uint32_t addr) {
    asm volatile("ldmatrix.sync.aligned.m8n8.x4.shared.b16 {%0,%1,%2,%3}, [%4];"
                 : "=r"(r[0]), "=r"(r[1]), "=r"(r[2]), "=r"(r[3]) : "r"(addr));
}
__device__ __forceinline__ void hmma(float4& d, const uint32_t a[4], const uint32_t* b) {
    asm volatile("mma.sync.aligned.m16n8k16.row.col.f32.bf16.bf16.f32 "
                 "{%0,%1,%2,%3}, {%4,%5,%6,%7}, {%8,%9}, {%0,%1,%2,%3};"
                 : "+f"(d.x), "+f"(d.y), "+f"(d.z), "+f"(d.w)
                 : "r"(a[0]), "r"(a[1]), "r"(a[2]), "r"(a[3]), "r"(b[0]), "r"(b[1]));
}

// split fp32 -> bf16 hi + bf16 residual, pack pairs into u32
__device__ __forceinline__ void split2(float x, float y, uint32_t& hi, uint32_t& lo) {
    __nv_bfloat16 hx = __float2bfloat16(x);
    __nv_bfloat16 hy = __float2bfloat16(y);
    __nv_bfloat16 lx = __float2bfloat16(x - __bfloat162float(hx));
    __nv_bfloat16 ly = __float2bfloat16(y - __bfloat162float(hy));
    hi = (uint32_t)*(uint16_t*)&hx | ((uint32_t)*(uint16_t*)&hy << 16);
    lo = (uint32_t)*(uint16_t*)&lx | ((uint32_t)*(uint16_t*)&ly << 16);
}

// ---------------- input-gate GEMM via mma.sync bf16x3 (fp32-accurate) ----------------
// Double-buffered A staging: ONE __syncthreads per k-step.
#define SW_HI   0
#define SW_LO   33792
#define SA_HI   67584     // + bufsel*12288
#define SA_LO   73728     // = SA_HI + 6144
#define SBIAS   92160
#define SM_GEMM 92416
#define WSTRIDE 528   // bytes per gate row (256 bf16 + 8 pad)

__global__ __launch_bounds__(256, 2) void gemm_hmma(
    const float* __restrict__ A, const float* __restrict__ W,
    const float* __restrict__ bias, float* __restrict__ C)
{
    extern __shared__ char sm[];
    const uint32_t sb = smem_u32(sm);
    const int tid  = threadIdx.x;
    const int lane = tid & 31, warp = tid >> 5;
    const int wm = warp >> 1, wn = warp & 1;
    const int g0 = blockIdx.x * 64;

    // one-time: W tile fp32 -> bf16 hi/lo SMEM
    {
        const int r = tid >> 2, kq = tid & 3;
        const float4* wp = (const float4*)(W + (size_t)(g0 + r) * 256 + kq * 64);
        char* dh = sm + SW_HI + r * WSTRIDE + kq * 128;
        char* dl = sm + SW_LO + r * WSTRIDE + kq * 128;
#pragma unroll
        for (int kk = 0; kk < 16; ++kk) {
            float4 v = wp[kk];
            uint2 h, l;
            split2(v.x, v.y, h.x, l.x);
            split2(v.z, v.w, h.y, l.y);
            *(uint2*)(dh + kk * 8) = h;
            *(uint2*)(dl + kk * 8) = l;
        }
    }
    if (tid < 64) ((float*)(sm + SBIAS))[tid] = bias[g0 + tid];

    const int lq = lane >> 3, l8 = lane & 7;
    const uint32_t arow = (uint32_t)((lq & 1) * 8 + l8);
    const uint32_t akh  = (uint32_t)((lq >> 1) * 16);
    const uint32_t bgat = (uint32_t)((lq >> 1) * 8 + l8);
    const uint32_t bkh  = (uint32_t)((lq & 1) * 8);
    const int grp = lane >> 2, tig = lane & 3;

    __syncthreads();

    for (int rt = blockIdx.y; rt < 1024; rt += 24) {
        const float* Ab = A + (size_t)rt * 128 * 256;
        const int prow = tid >> 1, phalf = tid & 1;

        float4 pa0, pa1;
        {
            const float4* ap = (const float4*)(Ab + (size_t)prow * 256 + phalf * 8);
            pa0 = ap[0]; pa1 = ap[1];
        }

        float4 d[2][4];
#pragma unroll
        for (int i = 0; i < 2; ++i)
#pragma unroll
            for (int j = 0; j < 4; ++j) d[i][j] = float4{0.f, 0.f, 0.f, 0.f};

        for (int ks = 0; ks < 16; ++ks) {
            const uint32_t bsel = (uint32_t)(ks & 1) * 12288u;
            {
                uint4 h, l;
                split2(pa0.x, pa0.y, h.x, l.x);
                split2(pa0.z, pa0.w, h.y, l.y);
                split2(pa1.x, pa1.y, h.z, l.z);
                split2(pa1.z, pa1.w, h.w, l.w);
                *(uint4*)(sm + SA_HI + bsel + prow * 48 + phalf * 16) = h;
                *(uint4*)(sm + SA_LO + bsel + prow * 48 + phalf * 16) = l;
            }
            if (ks + 1 < 16) {
                const float4* ap = (const float4*)(Ab + (size_t)prow * 256 + (ks + 1) * 16 + phalf * 8);
                pa0 = ap[0]; pa1 = ap[1];
            }
            __syncthreads();

            uint32_t ah[2][4], al[2][4], bhr[2][4], blr[2][4];
#pragma unroll
            for (int mf = 0; mf < 2; ++mf) {
                uint32_t off = (uint32_t)((wm * 32 + mf * 16 + arow) * 48) + akh;
                ldsm4(ah[mf], sb + SA_HI + bsel + off);
                ldsm4(al[mf], sb + SA_LO + bsel + off);
            }
#pragma unroll
            for (int bp = 0; bp < 2; ++bp) {
                uint32_t off = (uint32_t)((wn * 32 + bp * 16 + bgat) * WSTRIDE)
                             + (uint32_t)((ks * 16 + bkh) * 2);
                ldsm4(bhr[bp], sb + SW_HI + off);
                ldsm4(blr[bp], sb + SW_LO + off);
            }
#pragma unroll
            for (int mf = 0; mf < 2; ++mf)
#pragma unroll
                for (int nf = 0; nf < 4; ++nf) {
                    const uint32_t* bh = &bhr[nf >> 1][(nf & 1) * 2];
                    const uint32_t* bl = &blr[nf >> 1][(nf & 1) * 2];
                    hmma(d[mf][nf], ah[mf], bh);
                    hmma(d[mf][nf], ah[mf], bl);
                    hmma(d[mf][nf], al[mf], bh);
                }
        }

        const float* bs = (const float*)(sm + SBIAS);
#pragma unroll
        for (int mf = 0; mf < 2; ++mf) {
            size_t row = (size_t)rt * 128 + wm * 32 + mf * 16 + grp;
#pragma unroll
            for (int nf = 0; nf < 4; ++nf) {
                int gc = wn * 32 + nf * 8 + 2 * tig;
                float bx = bs[gc], by = bs[gc + 1];
                float4 v = d[mf][nf];
                *(float2*)(C + row * 768 + g0 + gc)       = float2{v.x + bx, v.y + by};
                *(float2*)(C + (row + 8) * 768 + g0 + gc) = float2{v.z + bx, v.w + by};
            }
        }
    }
}

// ---------------- GRU recurrence v6: TWO independent row-pipelines per cluster ----------------
// Cluster of 4 CTAs owns 4 batch rows; CTA rank owns h columns [rank*64, +64).
// The 4 rows are INDEPENDENT recurrences (shared weights). Pipeline A = rows {0,1},
// pipeline B = rows {2,3}, phase-offset by half a step:
//   dotA(t)[waitA] -> BAR -> pubB(t-1) -> epiA(t) -> dotB(t)[waitB] -> BAR -> pubA(t) -> epiB(t)
// Each pipeline's publish->wait window (fence + DSMEM flight + wake) is hidden under
// the other pipeline's epilogue + local-quarter dot. Same BARs/step (2), same FMA
// total, same 64 reg-resident r/z weights per thread (weights are row-independent).
// Publishes: premapped release-arrives from lanes 0-3 of warp 0 (parallel, not
// tid0-serialized); fence stays on warp 0 only (off other warps' critical path).
#define RSM_WN    0        // n-gate weights: [k4(64)][c(64)] float4 = 16384 floats
#define RSM_HA    16384    // hA: [2 parity][2 rows][256] = 1024 floats
#define RSM_HB    17408    // hB: same
#define RSM_GHA   18432    // sGhA: [e(8)][g(3)][r(2)][c(64)] = 3072 floats
#define RSM_GHB   21504    // sGhB: same
#define RSM_MBAR  24576    // mbarA (8B), then mbarB (8B)
#define REC_SMEM  (24576*4 + 64)

__global__ __launch_bounds__(512, 1) __cluster_dims__(4, 1, 1)
void gru_rec(const float* __restrict__ gx, const float* __restrict__ Whh,
             const float* __restrict__ bhh, float* __restrict__ out,
             float* __restrict__ hid)
{
    extern __shared__ float smem[];
    float4* sWn4 = (float4*)smem;
    float*  sHA  = smem + RSM_HA;
    float*  sHB  = smem + RSM_HB;
    float*  sGhA = smem + RSM_GHA;
    float*  sGhB = smem + RSM_GHB;
    const uint32_t mbarA = smem_u32(smem) + RSM_MBAR * 4;
    const uint32_t mbarB = mbarA + 8;

    const uint32_t rank = cl_rank();
    const int b0  = (blockIdx.x >> 2) * 4;
    const int tid = threadIdx.x;
    const int e   = tid >> 6;          // k-eighth (warp-pair uniform)
    const int c   = tid & 63;          // column within this CTA's 64-col chunk

    if (tid == 0) { mbar_init(mbarA, 4); mbar_init(mbarB, 4); }

    // n-gate weights -> SMEM [k4][c] float4
    for (int idx = tid; idx < 4096; idx += 512) {
        int k4 = idx >> 6, j = idx & 63;
        sWn4[idx] = ((const float4*)Whh)[(size_t)(512 + rank * 64 + j) * 64 + k4];
    }
    for (int i = tid; i < 1024; i += 512) { sHA[i] = 0.f; sHB[i] = 0.f; }

    // r,z gate weights -> 64 registers, quarter-visit order (q = rank+qi mod 4),
    // k in [q*64 + e*8, +8) per visit
    u64t wrR[16], wrZ[16];
#pragma unroll
    for (int qi = 0; qi < 4; ++qi) {
        const int q = ((int)rank + qi) & 3;
        const float* wbR = Whh + (size_t)(rank * 64 + c) * 256 + q * 64 + e * 8;
        const float* wbZ = wbR + 256 * 256;
#pragma unroll
        for (int kk = 0; kk < 2; ++kk) {
            ulonglong2 a = *(const ulonglong2*)(wbR + kk * 4);
            ulonglong2 b = *(const ulonglong2*)(wbZ + kk * 4);
            wrR[qi * 4 + 2 * kk] = a.x; wrR[qi * 4 + 2 * kk + 1] = a.y;
            wrZ[qi * 4 + 2 * kk] = b.x; wrZ[qi * 4 + 2 * kk + 1] = b.y;
        }
    }

    // epilogue roles: tid<128 -> pipeline A element (erow in {0,1}); tid in
    // [128,256) -> pipeline B element. One element (row, col) each.
    const int epiPipe = (tid >> 7) & 1;          // 0 = A, 1 = B (valid for tid<256)
    const int erow = (tid >> 6) & 1;
    const int ecol = tid & 63;
    const int growb = b0 + epiPipe * 2 + erow;   // global batch row
    float bR = 0.f, bZ = 0.f, bN = 0.f;
    if (tid < 256) {
        bR = bhh[rank * 64 + ecol];
        bZ = bhh[256 + rank * 64 + ecol];
        bN = bhh[512 + rank * 64 + ecol];
    }
    const size_t gxBase  = ((size_t)growb * 1024) * 768 + rank * 64 + ecol;
    const size_t outBase = ((size_t)growb * 1024) * 256 + rank * 64 + ecol;

    float gxr = 0.f, gxz = 0.f, gxn = 0.f;
    if (tid < 256) {
        gxr = gx[gxBase];
        gxz = gx[gxBase + 256];
        gxn = gx[gxBase + 512];
    }

    // premapped peer addresses
    // epilogue threads: 3 peer h-element addresses (parity-0 base, bytes)
    uint32_t peerH[3];
    if (tid < 256) {
        float* hbase = (epiPipe == 0 ? sHA : sHB);
        uint32_t la = smem_u32(hbase + erow * 256 + rank * 64 + ecol);
        int j = 0;
#pragma unroll
        for (int pr = 0; pr < 4; ++pr)
            if (pr != (int)rank) peerH[j++] = cl_map(la, (uint32_t)pr);
    }
    // publish threads: lanes 0-3 of warp 0 premap both mbars at peer = lane
    uint32_t pmbA = 0, pmbB = 0;
    if (tid < 4) {
        pmbA = cl_map(mbarA, (uint32_t)tid);
        pmbB = cl_map(mbarB, (uint32_t)tid);
    }

    cl_sync();  // weights, zeroed h, mbar inits visible cluster-wide

    for (int t = 0; t < 1024; ++t) {
        const uint32_t hoff  = (uint32_t)(t & 1) * 512;        // floats
        const uint32_t hoffN = (uint32_t)((t + 1) & 1) * 2048; // bytes, next buffer

        // ================= pipeline A: dot =================
        {
            const float* hbuf = sHA + hoff;
            u64t aR[2], aZ[2], aN[2];
#pragma unroll
            for (int i = 0; i < 2; ++i) { aR[i] = 0ull; aZ[i] = 0ull; aN[i] = 0ull; }
#pragma unroll
            for (int qi = 0; qi < 4; ++qi) {
                if (qi == 1 && t > 0)
                    mbar_wait_parity_cluster(mbarA, (uint32_t)((t - 1) & 1));
                const int q = ((int)rank + qi) & 3;
                const float*  hb = hbuf + q * 64 + e * 8;
                const float4* wn = sWn4 + (q * 16 + e * 2) * 64 + c;
#pragma unroll
                for (int kk = 0; kk < 2; ++kk) {
                    ulonglong2 wnv = *(const ulonglong2*)(wn + kk * 64);
                    u64t wr0 = wrR[qi * 4 + 2 * kk], wr1 = wrR[qi * 4 + 2 * kk + 1];
                    u64t wz0 = wrZ[qi * 4 + 2 * kk], wz1 = wrZ[qi * 4 + 2 * kk + 1];
#pragma unroll
                    for (int r = 0; r < 2; ++r) {
                        ulonglong2 hv = *(const ulonglong2*)(hb + r * 256 + kk * 4);
                        aR[r] = ffma2(wr0, hv.x, aR[r]);
                        aR[r] = ffma2(wr1, hv.y, aR[r]);
                        aZ[r] = ffma2(wz0, hv.x, aZ[r]);
                        aZ[r] = ffma2(wz1, hv.y, aZ[r]);
                        aN[r] = ffma2(wnv.x, hv.x, aN[r]);
                        aN[r] = ffma2(wnv.y, hv.y, aN[r]);
                    }
                }
            }
            float* sg = sGhA + e * 384 + c;   // [e][g][r][c]
#pragma unroll
            for (int r = 0; r < 2; ++r) {
                float2 p0 = unpack2(aR[r]);
                float2 p1 = unpack2(aZ[r]);
                float2 p2 = unpack2(aN[r]);
                sg[r * 64]       = p0.x + p0.y;
                sg[128 + r * 64] = p1.x + p1.y;
                sg[256 + r * 64] = p2.x + p2.y;
            }
        }
        __syncthreads();   // closes sGhA writes AND epiB(t-1) h-stores

        // publish B(t-1): lanes 0-3 of warp 0 (fence only on warp 0's path)
        if (t > 0 && tid < 32) {
            asm volatile("fence.acq_rel.cluster;" ::: "memory");
            if (tid < 4) mbar_arrive_rel_pre(pmbB);
        }

        // ================= pipeline A: epilogue (tid<128) =================
        if (tid < 128) {
            const int o = erow * 64 + ecol;
            float ghr = 0.f, ghz = 0.f, ghn = 0.f;
#pragma unroll
            for (int ee = 0; ee < 8; ++ee) {
                ghr += sGhA[ee * 384 + o];
                ghz += sGhA[ee * 384 + 128 + o];
                ghn += sGhA[ee * 384 + 256 + o];
            }
            float r  = fast_sigmoid(gxr + ghr + bR);
            float z  = fast_sigmoid(gxz + ghz + bZ);
            float hp = sHA[hoff + erow * 256 + rank * 64 + ecol];
            float n  = fast_tanh(fmaf(r, ghn + bN, gxn));
            float hnew = fmaf(z, hp - n, n);

            sHA[(hoffN >> 2) + erow * 256 + rank * 64 + ecol] = hnew;
#pragma unroll
            for (int j = 0; j < 3; ++j) st_cl_f32(peerH[j] + hoffN, hnew);

            out[outBase + (size_t)t * 256] = hnew;
            if (t == 1023) hid[(size_t)growb * 256 + rank * 64 + ecol] = hnew;
            else {
                size_t gb = gxBase + (size_t)(t + 1) * 768;
                gxr = gx[gb]; gxz = gx[gb + 256]; gxn = gx[gb + 512];
            }
        }

        // ================= pipeline B: dot =================
        {
            const float* hbuf = sHB + hoff;
            u64t aR[2], aZ[2], aN[2];
#pragma unroll
            for (int i = 0; i < 2; ++i) { aR[i] = 0ull; aZ[i] = 0ull; aN[i] = 0ull; }
#pragma unroll
            for (int qi = 0; qi < 4; ++qi) {
                if (qi == 1 && t > 0)
                    mbar_wait_parity_cluster(mbarB, (uint32_t)((t - 1) & 1));
                const int q = ((int)rank + qi) & 3;
                const float*  hb = hbuf + q * 64 + e * 8;
                const float4* wn = sWn4 + (q * 16 + e * 2) * 64 + c;
#pragma unroll
                for (int kk = 0; kk < 2; ++kk) {
                    ulonglong2 wnv = *(const ulonglong2*)(wn + kk * 64);
                    u64t wr0 = wrR[qi * 4 + 2 * kk], wr1 = wrR[qi * 4 + 2 * kk + 1];
                    u64t wz0 = wrZ[qi * 4 + 2 * kk], wz1 = wrZ[qi * 4 + 2 * kk + 1];
#pragma unroll
                    for (int r = 0; r < 2; ++r) {
                        ulonglong2 hv = *(const ulonglong2*)(hb + r * 256 + kk * 4);
                        aR[r] = ffma2(wr0, hv.x, aR[r]);
                        aR[r] = ffma2(wr1, hv.y, aR[r]);
                        aZ[r] = ffma2(wz0, hv.x, aZ[r]);
                        aZ[r] = ffma2(wz1, hv.y, aZ[r]);
                        aN[r] = ffma2(wnv.x, hv.x, aN[r]);
                        aN[r] = ffma2(wnv.y, hv.y, aN[r]);
                    }
                }
            }
            float* sg = sGhB + e * 384 + c;
#pragma unroll
            for (int r = 0; r < 2; ++r) {
                float2 p0 = unpack2(aR[r]);
                float2 p1 = unpack2(aZ[r]);
                float2 p2 = unpack2(aN[r]);
                sg[r * 64]       = p0.x + p0.y;
                sg[128 + r * 64] = p1.x + p1.y;
                sg[256 + r * 64] = p2.x + p2.y;
            }
        }
        __syncthreads();   // closes sGhB writes AND epiA(t) h-stores

        // publish A(t)
        if (tid < 32) {
            asm volatile("fence.acq_rel.cluster;" ::: "memory");
            if (tid < 4) mbar_arrive_rel_pre(pmbA);
        }

        // ================= pipeline B: epilogue (tid in [128,256)) =================
        if (tid >= 128 && tid < 256) {
            const int o = erow * 64 + ecol;
            float ghr = 0.f, ghz = 0.f, ghn = 0.f;
#pragma unroll
            for (int ee = 0; ee < 8; ++ee) {
                ghr += sGhB[ee * 384 + o];
                ghz += sGhB[ee * 384 + 128 + o];
                ghn += sGhB[ee * 384 + 256 + o];
            }
            float r  = fast_sigmoid(gxr + ghr + bR);
            float z  = fast_sigmoid(gxz + ghz + bZ);
            float hp = sHB[hoff + erow * 256 + rank * 64 + ecol];
            float n  = fast_tanh(fmaf(r, ghn + bN, gxn));
            float hnew = fmaf(z, hp - n, n);

            sHB[(hoffN >> 2) + erow * 256 + rank * 64 + ecol] = hnew;
#pragma unroll
            for (int j = 0; j < 3; ++j) st_cl_f32(peerH[j] + hoffN, hnew);

            out[outBase + (size_t)t * 256] = hnew;
            if (t == 1023) hid[(size_t)growb * 256 + rank * 64 + ecol] = hnew;
            else {
                size_t gb = gxBase + (size_t)(t + 1) * 768;
                gxr = gx[gb]; gxz = gx[gb + 256]; gxn = gx[gb + 512];
            }
        }
        // NOTE: epiB(t)'s stores are closed by the FIRST __syncthreads of step t+1
        // before publish B(t) fires there — the half-step offset in action.
    }

    cl_sync();  // no CTA exits while peers may still target its SMEM
}

// ---------------- launch ----------------
extern "C" void kernel_launch(void* const* d_in, const int* in_sizes, int n_in,
                              void* d_out, int out_size)
{
    const float* X      = (const float*)d_in[0];
    const float* w_ih_0 = (const float*)d_in[1];
    const float* w_hh_0 = (const float*)d_in[2];
    const float* b_ih_0 = (const float*)d_in[3];
    const float* b_hh_0 = (const float*)d_in[4];
    const float* w_ih_1 = (const float*)d_in[5];
    const float* w_hh_1 = (const float*)d_in[6];
    const float* b_ih_1 = (const float*)d_in[7];
    const float* b_hh_1 = (const float*)d_in[8];

    float* out1 = (float*)d_out;
    float* hid  = out1 + (size_t)ROWS * Mm;

    float *gx = nullptr, *o0 = nullptr;
    cudaGetSymbolAddress((void**)&gx, g_gx);
    cudaGetSymbolAddress((void**)&o0, g_out0);

    cudaFuncSetAttribute(gru_rec, cudaFuncAttributeMaxDynamicSharedMemorySize, REC_SMEM);
    cudaFuncSetAttribute(gemm_hmma, cudaFuncAttributeMaxDynamicSharedMemorySize, SM_GEMM);

    dim3 ggrid(12, 24);   // 12 gate-tiles x 24 row-streams

    // layer 0
    gemm_hmma<<<ggrid, 256, SM_GEMM>>>(X, w_ih_0, b_ih_0, gx);
    gru_rec<<<128, 512, REC_SMEM>>>(gx, w_hh_0, b_hh_0, o0, hid);
    // layer 1
    gemm_hmma<<<ggrid, 256, SM_GEMM>>>(o0, w_ih_1, b_ih_1, gx);
    gru_rec<<<128, 512, REC_SMEM>>>(gx, w_hh_1, b_hh_1, out1, hid + (size_t)Bb * Mm);
}